// round 14
// baseline (speedup 1.0000x reference)
#include <cuda_runtime.h>
#include <cuda_bf16.h>
#include <cstddef>
#include <cstdint>

// ---------------------------------------------------------------------------
// Problem constants: B=4, S=2048, D=1024, HEADS=16, d_k=64, scale=8
// ---------------------------------------------------------------------------
#define BB 4
#define SS 2048
#define DD 1024
#define MM (BB * SS)          // 8192
#define NHEAD 16
#define DK 64

// Scratch buffers
__device__ float g_q[MM * DD];
__device__ float g_k[MM * DD];
__device__ float g_v[MM * DD];
__device__ float g_ctx[MM * DD];
__device__ float g_qa[MM * DD];
__device__ float g_ka[MM * DD];
__device__ float g_va[MM * DD];
__device__ float g_wq[DD * DD];
__device__ float g_wk[DD * DD];
__device__ float g_wv[DD * DD];
__device__ float g_wo[DD * DD];

// ---------------------------------------------------------------------------
// helpers
// ---------------------------------------------------------------------------
__device__ __forceinline__ unsigned f2tf32(float x) {
    unsigned y;
    asm("cvt.rna.tf32.f32 %0, %1;" : "=r"(y) : "f"(x));
    return y;
}

__device__ __forceinline__ float ex2(float x) {
    float y;
    asm("ex2.approx.f32 %0, %1;" : "=f"(y) : "f"(x));
    return y;
}

__device__ __forceinline__ void mma_tf32(float* d, const unsigned* a,
                                         const unsigned* b, const float* c) {
    asm volatile(
        "mma.sync.aligned.m16n8k8.row.col.f32.tf32.tf32.f32 "
        "{%0,%1,%2,%3},{%4,%5,%6,%7},{%8,%9},{%10,%11,%12,%13};\n"
        : "=f"(d[0]), "=f"(d[1]), "=f"(d[2]), "=f"(d[3])
        : "r"(a[0]), "r"(a[1]), "r"(a[2]), "r"(a[3]),
          "r"(b[0]), "r"(b[1]),
          "f"(c[0]), "f"(c[1]), "f"(c[2]), "f"(c[3]));
}

__device__ __forceinline__ void cp16(unsigned dst, const float* src) {
    asm volatile("cp.async.cg.shared.global [%0], [%1], 16;\n"
                 :: "r"(dst), "l"(src));
}
#define CP_COMMIT() asm volatile("cp.async.commit_group;\n")
#define CP_WAIT(n)  asm volatile("cp.async.wait_group %0;\n" :: "n"(n))

// ---------------------------------------------------------------------------
// Fused elementwise RNA-round to the tf32 grid (z-indexed buffer select).
// ---------------------------------------------------------------------------
__global__ __launch_bounds__(256) void round_tf32_x3(
    const float4* __restrict__ s0, const float4* __restrict__ s1,
    const float4* __restrict__ s2,
    float4* __restrict__ d0, float4* __restrict__ d1, float4* __restrict__ d2,
    int n4)
{
    const int z = blockIdx.z;
    const float4* src = (z == 0) ? s0 : (z == 1) ? s1 : s2;
    float4*       dst = (z == 0) ? d0 : (z == 1) ? d1 : d2;
    const int i = blockIdx.x * blockDim.x + threadIdx.x;
    if (i < n4) {
        float4 v = src[i];
        v.x = __uint_as_float(f2tf32(v.x));
        v.y = __uint_as_float(f2tf32(v.y));
        v.z = __uint_as_float(f2tf32(v.z));
        v.w = __uint_as_float(f2tf32(v.w));
        dst[i] = v;
    }
}

__global__ __launch_bounds__(256) void round_tf32_x4(
    const float4* __restrict__ s0, const float4* __restrict__ s1,
    const float4* __restrict__ s2, const float4* __restrict__ s3,
    float4* __restrict__ d0, float4* __restrict__ d1,
    float4* __restrict__ d2, float4* __restrict__ d3,
    int n4)
{
    const int z = blockIdx.z;
    const float4* src = (z == 0) ? s0 : (z == 1) ? s1 : (z == 2) ? s2 : s3;
    float4*       dst = (z == 0) ? d0 : (z == 1) ? d1 : (z == 2) ? d2 : d3;
    const int i = blockIdx.x * blockDim.x + threadIdx.x;
    if (i < n4) {
        float4 v = src[i];
        v.x = __uint_as_float(f2tf32(v.x));
        v.y = __uint_as_float(f2tf32(v.y));
        v.z = __uint_as_float(f2tf32(v.z));
        v.w = __uint_as_float(f2tf32(v.w));
        dst[i] = v;
    }
}

// ---------------------------------------------------------------------------
// tf32 GEMM v5 with fused relu: C = relu(A @ B).  (unchanged from round 13)
// ---------------------------------------------------------------------------
#define G2LDA 36
#define G2LDB 136
#define G2_AS_WORDS (128 * G2LDA) // 4608
#define G2_BS_WORDS (32 * G2LDB)  // 4352
#define G2_STAGES 3
#define GEMM_SMEM_BYTES (G2_STAGES * (G2_AS_WORDS + G2_BS_WORDS) * 4)  // 107520

__device__ __forceinline__ void g2_fill(
    unsigned as_b, unsigned bs_b, int s,
    const float* __restrict__ Abase, const float* __restrict__ Bbase,
    int t, int tid, int N, int K)
{
    const size_t ko = (size_t)t * 32;
    #pragma unroll
    for (int i = 0; i < 8; ++i) {
        const int c  = i * 128 + tid;          // 0..1023
        const int ar = c >> 3, ak = (c & 7) * 4;
        const int br = c >> 5, bn = (c & 31) * 4;
        cp16(as_b + (unsigned)(s * G2_AS_WORDS + ar * G2LDA + ak) * 4,
             Abase + (size_t)ar * K + ko + ak);
        cp16(bs_b + (unsigned)(s * G2_BS_WORDS + br * G2LDB + bn) * 4,
             Bbase + (ko + br) * N + bn);
    }
}

__global__ __launch_bounds__(128, 2) void gemm_tf32_relu_v5(
    const float* __restrict__ A0, const float* __restrict__ B0, float* __restrict__ C0,
    const float* __restrict__ A1, const float* __restrict__ B1, float* __restrict__ C1,
    const float* __restrict__ A2, const float* __restrict__ B2, float* __restrict__ C2,
    int M, int N, int K)
{
    const int z = blockIdx.z;
    const float* A = (z == 0) ? A0 : (z == 1) ? A1 : A2;
    const float* B = (z == 0) ? B0 : (z == 1) ? B1 : B2;
    float*       C = (z == 0) ? C0 : (z == 1) ? C1 : C2;

    extern __shared__ unsigned gsm[];
    unsigned* AsBase = gsm;
    unsigned* BsBase = gsm + G2_STAGES * G2_AS_WORDS;
    const unsigned sb   = (unsigned)__cvta_generic_to_shared(gsm);
    const unsigned as_b = sb;
    const unsigned bs_b = sb + G2_STAGES * G2_AS_WORDS * 4;

    const int tid  = threadIdx.x;
    const int lane = tid & 31;
    const int warp = tid >> 5;
    const int wm   = warp & 1;
    const int wn   = warp >> 1;
    const int g    = lane >> 2;
    const int c4   = lane & 3;

    const int bm = blockIdx.y * 128;
    const int bn = blockIdx.x * 128;

    const float* Abase = A + (size_t)bm * K;
    const float* Bbase = B + bn;

    const int ntiles = K >> 5;   // 32

    g2_fill(as_b, bs_b, 0, Abase, Bbase, 0, tid, N, K);
    CP_COMMIT();
    g2_fill(as_b, bs_b, 1, Abase, Bbase, 1, tid, N, K);
    CP_COMMIT();

    float acc[4][8][4];
    #pragma unroll
    for (int mt = 0; mt < 4; ++mt)
        #pragma unroll
        for (int nt = 0; nt < 8; ++nt)
            #pragma unroll
            for (int i = 0; i < 4; ++i) acc[mt][nt][i] = 0.f;

    int cur = 0, fil = 2;
    for (int t = 0; t < ntiles; ++t) {
        CP_WAIT(1);
        __syncthreads();

        if (t + 2 < ntiles)
            g2_fill(as_b, bs_b, fil, Abase, Bbase, t + 2, tid, N, K);
        CP_COMMIT();

        const unsigned* As = AsBase + cur * G2_AS_WORDS;
        const unsigned* Bs = BsBase + cur * G2_BS_WORDS;

        #pragma unroll
        for (int ks = 0; ks < 4; ++ks) {
            const int col = ks * 8 + c4;
            unsigned af[4][4], bf[8][2];
            #pragma unroll
            for (int mt = 0; mt < 4; ++mt) {
                const int r = wm * 64 + mt * 16 + g;
                af[mt][0] = As[r * G2LDA + col];
                af[mt][1] = As[(r + 8) * G2LDA + col];
                af[mt][2] = As[r * G2LDA + col + 4];
                af[mt][3] = As[(r + 8) * G2LDA + col + 4];
            }
            #pragma unroll
            for (int nt = 0; nt < 8; ++nt) {
                const int n = wn * 64 + nt * 8 + g;
                bf[nt][0] = Bs[col * G2LDB + n];
                bf[nt][1] = Bs[(col + 4) * G2LDB + n];
            }
            #pragma unroll
            for (int mt = 0; mt < 4; ++mt)
                #pragma unroll
                for (int nt = 0; nt < 8; ++nt)
                    mma_tf32(acc[mt][nt], af[mt], bf[nt], acc[mt][nt]);
        }

        cur = (cur + 1 == 3) ? 0 : cur + 1;
        fil = (fil + 1 == 3) ? 0 : fil + 1;
    }

    #pragma unroll
    for (int mt = 0; mt < 4; ++mt) {
        const int r0 = bm + wm * 64 + mt * 16 + g;
        #pragma unroll
        for (int nt = 0; nt < 8; ++nt) {
            const int c0 = bn + wn * 64 + nt * 8 + 2 * c4;
            float2 v0, v1;
            v0.x = fmaxf(acc[mt][nt][0], 0.f);
            v0.y = fmaxf(acc[mt][nt][1], 0.f);
            v1.x = fmaxf(acc[mt][nt][2], 0.f);
            v1.y = fmaxf(acc[mt][nt][3], 0.f);
            *(float2*)&C[(size_t)r0 * N + c0] = v0;
            *(float2*)&C[(size_t)(r0 + 8) * N + c0] = v1;
        }
    }
}

// ---------------------------------------------------------------------------
// Tensor-core flash attention v7: GROUP-LOCAL pipeline.
// Per K-tile, for each of 4 column groups: QK (16 mma) -> V-frag prefetch ->
// fixed-base ex2 + Ps store -> syncwarp -> PV (16 mma). Group nt's MUFU burst
// is sandwiched between its own PV and group nt+1's QK tensor work, so the
// tensor pipe is never starved by the softmax chain. Live S registers shrink
// from 32 to 8. Per-accumulator mma order and l-summation order are identical
// to v6 -> bit-same result.
// ---------------------------------------------------------------------------
#define ALD 76
#define VLD 88
#define QTILE 128
#define KTILE 32
#define NT (SS / KTILE)   // 64
#define ATT_STAGES 3
#define ATT_SMEM_WORDS (QTILE * ALD + ATT_STAGES * KTILE * ALD + ATT_STAGES * KTILE * VLD)
#define ATT_SMEM_BYTES (ATT_SMEM_WORDS * 4)
#define QSCALE 0.1803368801111204f   // 0.125 * log2(e)

__global__ __launch_bounds__(128, 2) void attention_tc(
    const float* __restrict__ Qp, const float* __restrict__ Kp,
    const float* __restrict__ Vp, float* __restrict__ Ctx)
{
    extern __shared__ unsigned smu[];
    unsigned (*Qs)[ALD] = (unsigned(*)[ALD])smu;                      // 128 rows
    unsigned (*Ks)[KTILE][ALD] = (unsigned(*)[KTILE][ALD])(smu + QTILE * ALD);
    unsigned (*Vs)[KTILE][VLD] =
        (unsigned(*)[KTILE][VLD])(smu + QTILE * ALD + ATT_STAGES * KTILE * ALD);
    unsigned (*Ps)[ALD] = Qs;                                          // alias

    const unsigned sbase = (unsigned)__cvta_generic_to_shared(smu);
    const unsigned qs_b  = sbase;
    const unsigned ks_b  = sbase + QTILE * ALD * 4;
    const unsigned vs_b  = sbase + (QTILE * ALD + ATT_STAGES * KTILE * ALD) * 4;

    const int tid  = threadIdx.x;
    const int lane = tid & 31;
    const int warp = tid >> 5;     // 0..3
    const int g    = lane >> 2;
    const int c4   = lane & 3;
    const int rb   = warp * 32;    // this warp's 32-row q slab

    const int bh = blockIdx.y;
    const int b  = bh >> 4;
    const int h  = bh & 15;
    const int q0 = blockIdx.x * QTILE;

    const float* Qbase = Qp + (size_t)b * SS * DD + h * DK;
    const float* Kbase = Kp + (size_t)b * SS * DD + h * DK;
    const float* Vbase = Vp + (size_t)b * SS * DD + h * DK;

    // ---- prologue: group0 = Q + KV tile 0; group1 = KV tile 1 ----
    {
        #pragma unroll
        for (int i = 0; i < 16; ++i) {
            const int c = i * 128 + tid;
            const int r = c >> 4, col = (c & 15) * 4;
            cp16(qs_b + (unsigned)(r * ALD + col) * 4,
                 Qbase + (size_t)(q0 + r) * DD + col);
        }
        #pragma unroll
        for (int i = 0; i < 4; ++i) {
            const int c = i * 128 + tid;
            const int r = c >> 4, col = (c & 15) * 4;
            cp16(ks_b + (unsigned)(r * ALD + col) * 4,
                 Kbase + (size_t)r * DD + col);
            cp16(vs_b + (unsigned)(r * VLD + col) * 4,
                 Vbase + (size_t)r * DD + col);
        }
        CP_COMMIT();
        #pragma unroll
        for (int i = 0; i < 4; ++i) {
            const int c = i * 128 + tid;
            const int r = c >> 4, col = (c & 15) * 4;
            cp16(ks_b + (unsigned)((KTILE + r) * ALD + col) * 4,
                 Kbase + (size_t)(KTILE + r) * DD + col);
            cp16(vs_b + (unsigned)((KTILE + r) * VLD + col) * 4,
                 Vbase + (size_t)(KTILE + r) * DD + col);
        }
        CP_COMMIT();
    }
    CP_WAIT(1);           // Q + tile 0 resident
    __syncthreads();

    // ---- hoist Q fragments (Q read exactly once -> Ps alias safe) ----
    unsigned qf0[8][4], qf1[8][4];
    #pragma unroll
    for (int ks = 0; ks < 8; ++ks) {
        const int col = ks * 8 + c4;
        qf0[ks][0] = Qs[rb + g][col];
        qf0[ks][1] = Qs[rb + g + 8][col];
        qf0[ks][2] = Qs[rb + g][col + 4];
        qf0[ks][3] = Qs[rb + g + 8][col + 4];
        qf1[ks][0] = Qs[rb + 16 + g][col];
        qf1[ks][1] = Qs[rb + 24 + g][col];
        qf1[ks][2] = Qs[rb + 16 + g][col + 4];
        qf1[ks][3] = Qs[rb + 24 + g][col + 4];
    }

    float l00 = 0.f, l01 = 0.f, l10 = 0.f, l11 = 0.f;
    float o0[8][4], o1[8][4];
    #pragma unroll
    for (int nt = 0; nt < 8; ++nt)
        #pragma unroll
        for (int i = 0; i < 4; ++i) { o0[nt][i] = 0.f; o1[nt][i] = 0.f; }

    int cur = 0, fil = 2;
    for (int t = 0; t < NT; ++t) {
        CP_WAIT(1);         // tile t resident
        __syncthreads();    // publish tile t; all warps done reading slot fil

        if (t + 2 < NT) {
            const int k0 = (t + 2) * KTILE;
            #pragma unroll
            for (int i = 0; i < 4; ++i) {
                const int c = i * 128 + tid;
                const int r = c >> 4, col = (c & 15) * 4;
                cp16(ks_b + (unsigned)((fil * KTILE + r) * ALD + col) * 4,
                     Kbase + (size_t)(k0 + r) * DD + col);
                cp16(vs_b + (unsigned)((fil * KTILE + r) * VLD + col) * 4,
                     Vbase + (size_t)(k0 + r) * DD + col);
            }
        }
        CP_COMMIT();        // keep group counts aligned

        // ---- group-local pipeline: QK -> softmax -> PV per column group ----
        #pragma unroll
        for (int grp = 0; grp < 4; ++grp) {
            // QK for S-column group grp (K rows [8*grp, 8*grp+8))
            float s0[4] = {0.f, 0.f, 0.f, 0.f};
            float s1[4] = {0.f, 0.f, 0.f, 0.f};
            #pragma unroll
            for (int ks = 0; ks < 8; ++ks) {
                const int col = ks * 8 + c4;
                unsigned bf[2];
                bf[0] = Ks[cur][grp * 8 + g][col];
                bf[1] = Ks[cur][grp * 8 + g][col + 4];
                mma_tf32(s0, qf0[ks], bf, s0);
                mma_tf32(s1, qf1[ks], bf, s1);
            }

            // prefetch V fragments for this group's PV step (softmax-independent)
            const int vcol = grp * 8 + c4;
            unsigned vf[8][2];
            #pragma unroll
            for (int nt2 = 0; nt2 < 8; ++nt2) {
                vf[nt2][0] = Vs[cur][vcol][g + 8 * nt2];
                vf[nt2][1] = Vs[cur][vcol + 4][g + 8 * nt2];
            }

            // fixed-base softmax for group grp
            {
                float p0 = ex2(s0[0] * QSCALE);
                float p1 = ex2(s0[1] * QSCALE);
                float p2 = ex2(s0[2] * QSCALE);
                float p3 = ex2(s0[3] * QSCALE);
                l00 += p0 + p1; l01 += p2 + p3;
                *(uint2*)&Ps[rb + g][grp * 8 + 2 * c4] =
                    make_uint2(__float_as_uint(p0), __float_as_uint(p1));
                *(uint2*)&Ps[rb + g + 8][grp * 8 + 2 * c4] =
                    make_uint2(__float_as_uint(p2), __float_as_uint(p3));

                p0 = ex2(s1[0] * QSCALE);
                p1 = ex2(s1[1] * QSCALE);
                p2 = ex2(s1[2] * QSCALE);
                p3 = ex2(s1[3] * QSCALE);
                l10 += p0 + p1; l11 += p2 + p3;
                *(uint2*)&Ps[rb + 16 + g][grp * 8 + 2 * c4] =
                    make_uint2(__float_as_uint(p0), __float_as_uint(p1));
                *(uint2*)&Ps[rb + 24 + g][grp * 8 + 2 * c4] =
                    make_uint2(__float_as_uint(p2), __float_as_uint(p3));
            }
            __syncwarp();   // group grp's Ps stores visible within warp

            // PV ks-step = grp
            {
                unsigned pf0[4], pf1[4];
                pf0[0] = Ps[rb + g][vcol];
                pf0[1] = Ps[rb + g + 8][vcol];
                pf0[2] = Ps[rb + g][vcol + 4];
                pf0[3] = Ps[rb + g + 8][vcol + 4];
                pf1[0] = Ps[rb + 16 + g][vcol];
                pf1[1] = Ps[rb + 24 + g][vcol];
                pf1[2] = Ps[rb + 16 + g][vcol + 4];
                pf1[3] = Ps[rb + 24 + g][vcol + 4];
                #pragma unroll
                for (int nt2 = 0; nt2 < 8; ++nt2) {
                    mma_tf32(o0[nt2], pf0, vf[nt2], o0[nt2]);
                    mma_tf32(o1[nt2], pf1, vf[nt2], o1[nt2]);
                }
            }
        }

        cur = (cur + 1 == 3) ? 0 : cur + 1;
        fil = (fil + 1 == 3) ? 0 : fil + 1;
    }

    // ---- final l reduction (once) ----
    #pragma unroll
    for (int d = 1; d <= 2; d <<= 1) {
        l00 += __shfl_xor_sync(0xffffffffu, l00, d);
        l01 += __shfl_xor_sync(0xffffffffu, l01, d);
        l10 += __shfl_xor_sync(0xffffffffu, l10, d);
        l11 += __shfl_xor_sync(0xffffffffu, l11, d);
    }

    // ---- finalize: divide by l, RNA-round to tf32 grid, write ctx ----
    const float i00 = 1.f / l00, i01 = 1.f / l01;
    const float i10 = 1.f / l10, i11 = 1.f / l11;
    const int r0 = q0 + rb + g;
    #pragma unroll
    for (int nt = 0; nt < 8; ++nt) {
        const int col = h * DK + nt * 8 + 2 * c4;
        float2 w;
        w.x = __uint_as_float(f2tf32(o0[nt][0] * i00));
        w.y = __uint_as_float(f2tf32(o0[nt][1] * i00));
        *(float2*)&Ctx[((size_t)b * SS + r0) * DD + col] = w;
        w.x = __uint_as_float(f2tf32(o0[nt][2] * i01));
        w.y = __uint_as_float(f2tf32(o0[nt][3] * i01));
        *(float2*)&Ctx[((size_t)b * SS + r0 + 8) * DD + col] = w;
        w.x = __uint_as_float(f2tf32(o1[nt][0] * i10));
        w.y = __uint_as_float(f2tf32(o1[nt][1] * i10));
        *(float2*)&Ctx[((size_t)b * SS + r0 + 16) * DD + col] = w;
        w.x = __uint_as_float(f2tf32(o1[nt][2] * i11));
        w.y = __uint_as_float(f2tf32(o1[nt][3] * i11));
        *(float2*)&Ctx[((size_t)b * SS + r0 + 24) * DD + col] = w;
    }
}

// ---------------------------------------------------------------------------
// Launch
// ---------------------------------------------------------------------------
extern "C" void kernel_launch(void* const* d_in, const int* in_sizes, int n_in,
                              void* d_out, int out_size)
{
    const float* query = (const float*)d_in[0];
    const float* key   = (const float*)d_in[1];
    const float* value = (const float*)d_in[2];
    const float* Wq    = (const float*)d_in[3];
    const float* Wk    = (const float*)d_in[4];
    const float* Wv    = (const float*)d_in[5];
    const float* Wo    = (const float*)d_in[6];

    float *gq, *gk, *gv, *gc, *gqa, *gka, *gva, *gwq, *gwk, *gwv, *gwo;
    cudaGetSymbolAddress((void**)&gq,  g_q);
    cudaGetSymbolAddress((void**)&gk,  g_k);
    cudaGetSymbolAddress((void**)&gv,  g_v);
    cudaGetSymbolAddress((void**)&gc,  g_ctx);
    cudaGetSymbolAddress((void**)&gqa, g_qa);
    cudaGetSymbolAddress((void**)&gka, g_ka);
    cudaGetSymbolAddress((void**)&gva, g_va);
    cudaGetSymbolAddress((void**)&gwq, g_wq);
    cudaGetSymbolAddress((void**)&gwk, g_wk);
    cudaGetSymbolAddress((void**)&gwv, g_wv);
    cudaGetSymbolAddress((void**)&gwo, g_wo);

    // ---- pre-round all GEMM operands onto the tf32 grid (RNA), fused ----
    const int act4 = MM * DD / 4;   // 2M float4
    const int w4   = DD * DD / 4;   // 256K float4
    {
        dim3 grid_a((act4 + 255) / 256, 1, 3);
        round_tf32_x3<<<grid_a, 256>>>(
            (const float4*)query, (const float4*)key, (const float4*)value,
            (float4*)gqa, (float4*)gka, (float4*)gva, act4);
        dim3 grid_w((w4 + 255) / 256, 1, 4);
        round_tf32_x4<<<grid_w, 256>>>(
            (const float4*)Wq, (const float4*)Wk, (const float4*)Wv, (const float4*)Wo,
            (float4*)gwq, (float4*)gwk, (float4*)gwv, (float4*)gwo, w4);
    }

    cudaFuncSetAttribute(gemm_tf32_relu_v5,
                         cudaFuncAttributeMaxDynamicSharedMemorySize,
                         GEMM_SMEM_BYTES);

    // ---- fused QKV projections: one launch, z selects the GEMM ----
    {
        dim3 grid(DD / 128, MM / 128, 3);   // (8, 64, 3)
        gemm_tf32_relu_v5<<<grid, 128, GEMM_SMEM_BYTES>>>(
            gqa, gwq, gq,
            gka, gwk, gk,
            gva, gwv, gv,
            MM, DD, DD);
    }

    cudaFuncSetAttribute(attention_tc,
                         cudaFuncAttributeMaxDynamicSharedMemorySize,
                         ATT_SMEM_BYTES);
    attention_tc<<<dim3(SS / QTILE, BB * NHEAD), 128, ATT_SMEM_BYTES>>>(gq, gk, gv, gc);

    // ---- output projection ----
    {
        dim3 grid(DD / 128, MM / 128, 1);
        gemm_tf32_relu_v5<<<grid, 128, GEMM_SMEM_BYTES>>>(
            gc, gwo, (float*)d_out,
            gc, gwo, (float*)d_out,
            gc, gwo, (float*)d_out,
            MM, DD, DD);
    }
}

// round 16
// speedup vs baseline: 1.0296x; 1.0296x over previous
#include <cuda_runtime.h>
#include <cuda_bf16.h>
#include <cstddef>
#include <cstdint>

// ---------------------------------------------------------------------------
// Problem constants: B=4, S=2048, D=1024, HEADS=16, d_k=64, scale=8
// ---------------------------------------------------------------------------
#define BB 4
#define SS 2048
#define DD 1024
#define MM (BB * SS)          // 8192
#define NHEAD 16
#define DK 64

// Scratch buffers
__device__ float g_q[MM * DD];
__device__ float g_k[MM * DD];
__device__ float g_v[MM * DD];
__device__ float g_ctx[MM * DD];
__device__ float g_qa[MM * DD];
__device__ float g_ka[MM * DD];
__device__ float g_va[MM * DD];
__device__ float g_wq[DD * DD];
__device__ float g_wk[DD * DD];
__device__ float g_wv[DD * DD];
__device__ float g_wo[DD * DD];

// ---------------------------------------------------------------------------
// helpers
// ---------------------------------------------------------------------------
__device__ __forceinline__ unsigned f2tf32(float x) {
    unsigned y;
    asm("cvt.rna.tf32.f32 %0, %1;" : "=r"(y) : "f"(x));
    return y;
}

__device__ __forceinline__ float ex2(float x) {
    float y;
    asm("ex2.approx.f32 %0, %1;" : "=f"(y) : "f"(x));
    return y;
}

__device__ __forceinline__ void mma_tf32(float* d, const unsigned* a,
                                         const unsigned* b, const float* c) {
    asm volatile(
        "mma.sync.aligned.m16n8k8.row.col.f32.tf32.tf32.f32 "
        "{%0,%1,%2,%3},{%4,%5,%6,%7},{%8,%9},{%10,%11,%12,%13};\n"
        : "=f"(d[0]), "=f"(d[1]), "=f"(d[2]), "=f"(d[3])
        : "r"(a[0]), "r"(a[1]), "r"(a[2]), "r"(a[3]),
          "r"(b[0]), "r"(b[1]),
          "f"(c[0]), "f"(c[1]), "f"(c[2]), "f"(c[3]));
}

__device__ __forceinline__ void cp16(unsigned dst, const float* src) {
    asm volatile("cp.async.cg.shared.global [%0], [%1], 16;\n"
                 :: "r"(dst), "l"(src));
}
#define CP_COMMIT() asm volatile("cp.async.commit_group;\n")
#define CP_WAIT(n)  asm volatile("cp.async.wait_group %0;\n" :: "n"(n))

// ---------------------------------------------------------------------------
// Fused elementwise RNA-round to the tf32 grid (z-indexed buffer select).
// ---------------------------------------------------------------------------
__global__ __launch_bounds__(256) void round_tf32_x3(
    const float4* __restrict__ s0, const float4* __restrict__ s1,
    const float4* __restrict__ s2,
    float4* __restrict__ d0, float4* __restrict__ d1, float4* __restrict__ d2,
    int n4)
{
    const int z = blockIdx.z;
    const float4* src = (z == 0) ? s0 : (z == 1) ? s1 : s2;
    float4*       dst = (z == 0) ? d0 : (z == 1) ? d1 : d2;
    const int i = blockIdx.x * blockDim.x + threadIdx.x;
    if (i < n4) {
        float4 v = src[i];
        v.x = __uint_as_float(f2tf32(v.x));
        v.y = __uint_as_float(f2tf32(v.y));
        v.z = __uint_as_float(f2tf32(v.z));
        v.w = __uint_as_float(f2tf32(v.w));
        dst[i] = v;
    }
}

__global__ __launch_bounds__(256) void round_tf32_x4(
    const float4* __restrict__ s0, const float4* __restrict__ s1,
    const float4* __restrict__ s2, const float4* __restrict__ s3,
    float4* __restrict__ d0, float4* __restrict__ d1,
    float4* __restrict__ d2, float4* __restrict__ d3,
    int n4)
{
    const int z = blockIdx.z;
    const float4* src = (z == 0) ? s0 : (z == 1) ? s1 : (z == 2) ? s2 : s3;
    float4*       dst = (z == 0) ? d0 : (z == 1) ? d1 : (z == 2) ? d2 : d3;
    const int i = blockIdx.x * blockDim.x + threadIdx.x;
    if (i < n4) {
        float4 v = src[i];
        v.x = __uint_as_float(f2tf32(v.x));
        v.y = __uint_as_float(f2tf32(v.y));
        v.z = __uint_as_float(f2tf32(v.z));
        v.w = __uint_as_float(f2tf32(v.w));
        dst[i] = v;
    }
}

// ---------------------------------------------------------------------------
// tf32 GEMM v5 with fused relu + optional epilogue scale on the z==0 GEMM:
// C = relu(A @ B) * sc.  (structure identical to round 13; scale0 lets the
// q-projection carry the softmax QSCALE for free.)
// ---------------------------------------------------------------------------
#define G2LDA 36
#define G2LDB 136
#define G2_AS_WORDS (128 * G2LDA) // 4608
#define G2_BS_WORDS (32 * G2LDB)  // 4352
#define G2_STAGES 3
#define GEMM_SMEM_BYTES (G2_STAGES * (G2_AS_WORDS + G2_BS_WORDS) * 4)  // 107520

__device__ __forceinline__ void g2_fill(
    unsigned as_b, unsigned bs_b, int s,
    const float* __restrict__ Abase, const float* __restrict__ Bbase,
    int t, int tid, int N, int K)
{
    const size_t ko = (size_t)t * 32;
    #pragma unroll
    for (int i = 0; i < 8; ++i) {
        const int c  = i * 128 + tid;          // 0..1023
        const int ar = c >> 3, ak = (c & 7) * 4;
        const int br = c >> 5, bn = (c & 31) * 4;
        cp16(as_b + (unsigned)(s * G2_AS_WORDS + ar * G2LDA + ak) * 4,
             Abase + (size_t)ar * K + ko + ak);
        cp16(bs_b + (unsigned)(s * G2_BS_WORDS + br * G2LDB + bn) * 4,
             Bbase + (ko + br) * N + bn);
    }
}

__global__ __launch_bounds__(128, 2) void gemm_tf32_relu_v5(
    const float* __restrict__ A0, const float* __restrict__ B0, float* __restrict__ C0,
    const float* __restrict__ A1, const float* __restrict__ B1, float* __restrict__ C1,
    const float* __restrict__ A2, const float* __restrict__ B2, float* __restrict__ C2,
    int M, int N, int K, float scale0)
{
    const int z = blockIdx.z;
    const float* A = (z == 0) ? A0 : (z == 1) ? A1 : A2;
    const float* B = (z == 0) ? B0 : (z == 1) ? B1 : B2;
    float*       C = (z == 0) ? C0 : (z == 1) ? C1 : C2;
    const float sc = (z == 0) ? scale0 : 1.0f;

    extern __shared__ unsigned gsm[];
    unsigned* AsBase = gsm;
    unsigned* BsBase = gsm + G2_STAGES * G2_AS_WORDS;
    const unsigned sb   = (unsigned)__cvta_generic_to_shared(gsm);
    const unsigned as_b = sb;
    const unsigned bs_b = sb + G2_STAGES * G2_AS_WORDS * 4;

    const int tid  = threadIdx.x;
    const int lane = tid & 31;
    const int warp = tid >> 5;
    const int wm   = warp & 1;
    const int wn   = warp >> 1;
    const int g    = lane >> 2;
    const int c4   = lane & 3;

    const int bm = blockIdx.y * 128;
    const int bn = blockIdx.x * 128;

    const float* Abase = A + (size_t)bm * K;
    const float* Bbase = B + bn;

    const int ntiles = K >> 5;   // 32

    g2_fill(as_b, bs_b, 0, Abase, Bbase, 0, tid, N, K);
    CP_COMMIT();
    g2_fill(as_b, bs_b, 1, Abase, Bbase, 1, tid, N, K);
    CP_COMMIT();

    float acc[4][8][4];
    #pragma unroll
    for (int mt = 0; mt < 4; ++mt)
        #pragma unroll
        for (int nt = 0; nt < 8; ++nt)
            #pragma unroll
            for (int i = 0; i < 4; ++i) acc[mt][nt][i] = 0.f;

    int cur = 0, fil = 2;
    for (int t = 0; t < ntiles; ++t) {
        CP_WAIT(1);
        __syncthreads();

        if (t + 2 < ntiles)
            g2_fill(as_b, bs_b, fil, Abase, Bbase, t + 2, tid, N, K);
        CP_COMMIT();

        const unsigned* As = AsBase + cur * G2_AS_WORDS;
        const unsigned* Bs = BsBase + cur * G2_BS_WORDS;

        #pragma unroll
        for (int ks = 0; ks < 4; ++ks) {
            const int col = ks * 8 + c4;
            unsigned af[4][4], bf[8][2];
            #pragma unroll
            for (int mt = 0; mt < 4; ++mt) {
                const int r = wm * 64 + mt * 16 + g;
                af[mt][0] = As[r * G2LDA + col];
                af[mt][1] = As[(r + 8) * G2LDA + col];
                af[mt][2] = As[r * G2LDA + col + 4];
                af[mt][3] = As[(r + 8) * G2LDA + col + 4];
            }
            #pragma unroll
            for (int nt = 0; nt < 8; ++nt) {
                const int n = wn * 64 + nt * 8 + g;
                bf[nt][0] = Bs[col * G2LDB + n];
                bf[nt][1] = Bs[(col + 4) * G2LDB + n];
            }
            #pragma unroll
            for (int mt = 0; mt < 4; ++mt)
                #pragma unroll
                for (int nt = 0; nt < 8; ++nt)
                    mma_tf32(acc[mt][nt], af[mt], bf[nt], acc[mt][nt]);
        }

        cur = (cur + 1 == 3) ? 0 : cur + 1;
        fil = (fil + 1 == 3) ? 0 : fil + 1;
    }

    #pragma unroll
    for (int mt = 0; mt < 4; ++mt) {
        const int r0 = bm + wm * 64 + mt * 16 + g;
        #pragma unroll
        for (int nt = 0; nt < 8; ++nt) {
            const int c0 = bn + wn * 64 + nt * 8 + 2 * c4;
            float2 v0, v1;
            v0.x = fmaxf(acc[mt][nt][0], 0.f) * sc;
            v0.y = fmaxf(acc[mt][nt][1], 0.f) * sc;
            v1.x = fmaxf(acc[mt][nt][2], 0.f) * sc;
            v1.y = fmaxf(acc[mt][nt][3], 0.f) * sc;
            *(float2*)&C[(size_t)r0 * N + c0] = v0;
            *(float2*)&C[(size_t)(r0 + 8) * N + c0] = v1;
        }
    }
}

// ---------------------------------------------------------------------------
// Tensor-core flash attention v8: round-13 structure (full QK, interleaved
// softmax+PV per column group) with two deltas:
//  - q arrives pre-scaled by QSCALE -> softmax is p = ex2(s), no FMUL.
//  - vf loads hoisted above the ex2 chain (independent of Ps; overlap MUFU).
// Epilogue RNA-rounds ctx (round-13 numerics discipline).
// ---------------------------------------------------------------------------
#define ALD 76
#define VLD 88
#define QTILE 128
#define KTILE 32
#define NT (SS / KTILE)   // 64
#define ATT_STAGES 3
#define ATT_SMEM_WORDS (QTILE * ALD + ATT_STAGES * KTILE * ALD + ATT_STAGES * KTILE * VLD)
#define ATT_SMEM_BYTES (ATT_SMEM_WORDS * 4)
#define QSCALE 0.1803368801111204f   // 0.125 * log2(e)

__global__ __launch_bounds__(128, 2) void attention_tc(
    const float* __restrict__ Qp, const float* __restrict__ Kp,
    const float* __restrict__ Vp, float* __restrict__ Ctx)
{
    extern __shared__ unsigned smu[];
    unsigned (*Qs)[ALD] = (unsigned(*)[ALD])smu;                      // 128 rows
    unsigned (*Ks)[KTILE][ALD] = (unsigned(*)[KTILE][ALD])(smu + QTILE * ALD);
    unsigned (*Vs)[KTILE][VLD] =
        (unsigned(*)[KTILE][VLD])(smu + QTILE * ALD + ATT_STAGES * KTILE * ALD);
    unsigned (*Ps)[ALD] = Qs;                                          // alias

    const unsigned sbase = (unsigned)__cvta_generic_to_shared(smu);
    const unsigned qs_b  = sbase;
    const unsigned ks_b  = sbase + QTILE * ALD * 4;
    const unsigned vs_b  = sbase + (QTILE * ALD + ATT_STAGES * KTILE * ALD) * 4;

    const int tid  = threadIdx.x;
    const int lane = tid & 31;
    const int warp = tid >> 5;     // 0..3
    const int g    = lane >> 2;
    const int c4   = lane & 3;
    const int rb   = warp * 32;    // this warp's 32-row q slab

    const int bh = blockIdx.y;
    const int b  = bh >> 4;
    const int h  = bh & 15;
    const int q0 = blockIdx.x * QTILE;

    const float* Qbase = Qp + (size_t)b * SS * DD + h * DK;
    const float* Kbase = Kp + (size_t)b * SS * DD + h * DK;
    const float* Vbase = Vp + (size_t)b * SS * DD + h * DK;

    // ---- prologue: group0 = Q + KV tile 0; group1 = KV tile 1 ----
    {
        #pragma unroll
        for (int i = 0; i < 16; ++i) {
            const int c = i * 128 + tid;
            const int r = c >> 4, col = (c & 15) * 4;
            cp16(qs_b + (unsigned)(r * ALD + col) * 4,
                 Qbase + (size_t)(q0 + r) * DD + col);
        }
        #pragma unroll
        for (int i = 0; i < 4; ++i) {
            const int c = i * 128 + tid;
            const int r = c >> 4, col = (c & 15) * 4;
            cp16(ks_b + (unsigned)(r * ALD + col) * 4,
                 Kbase + (size_t)r * DD + col);
            cp16(vs_b + (unsigned)(r * VLD + col) * 4,
                 Vbase + (size_t)r * DD + col);
        }
        CP_COMMIT();
        #pragma unroll
        for (int i = 0; i < 4; ++i) {
            const int c = i * 128 + tid;
            const int r = c >> 4, col = (c & 15) * 4;
            cp16(ks_b + (unsigned)((KTILE + r) * ALD + col) * 4,
                 Kbase + (size_t)(KTILE + r) * DD + col);
            cp16(vs_b + (unsigned)((KTILE + r) * VLD + col) * 4,
                 Vbase + (size_t)(KTILE + r) * DD + col);
        }
        CP_COMMIT();
    }
    CP_WAIT(1);           // Q + tile 0 resident
    __syncthreads();

    // ---- hoist Q fragments (Q read exactly once -> Ps alias safe) ----
    unsigned qf0[8][4], qf1[8][4];
    #pragma unroll
    for (int ks = 0; ks < 8; ++ks) {
        const int col = ks * 8 + c4;
        qf0[ks][0] = Qs[rb + g][col];
        qf0[ks][1] = Qs[rb + g + 8][col];
        qf0[ks][2] = Qs[rb + g][col + 4];
        qf0[ks][3] = Qs[rb + g + 8][col + 4];
        qf1[ks][0] = Qs[rb + 16 + g][col];
        qf1[ks][1] = Qs[rb + 24 + g][col];
        qf1[ks][2] = Qs[rb + 16 + g][col + 4];
        qf1[ks][3] = Qs[rb + 24 + g][col + 4];
    }

    float l00 = 0.f, l01 = 0.f, l10 = 0.f, l11 = 0.f;
    float o0[8][4], o1[8][4];
    #pragma unroll
    for (int nt = 0; nt < 8; ++nt)
        #pragma unroll
        for (int i = 0; i < 4; ++i) { o0[nt][i] = 0.f; o1[nt][i] = 0.f; }

    int cur = 0, fil = 2;
    for (int t = 0; t < NT; ++t) {
        CP_WAIT(1);         // tile t resident
        __syncthreads();    // publish tile t; all warps done reading slot fil

        if (t + 2 < NT) {
            const int k0 = (t + 2) * KTILE;
            #pragma unroll
            for (int i = 0; i < 4; ++i) {
                const int c = i * 128 + tid;
                const int r = c >> 4, col = (c & 15) * 4;
                cp16(ks_b + (unsigned)((fil * KTILE + r) * ALD + col) * 4,
                     Kbase + (size_t)(k0 + r) * DD + col);
                cp16(vs_b + (unsigned)((fil * KTILE + r) * VLD + col) * 4,
                     Vbase + (size_t)(k0 + r) * DD + col);
            }
        }
        CP_COMMIT();        // keep group counts aligned

        // ---- S = Q @ K^T (full tile: deep independent mma window) ----
        float s0[4][4], s1[4][4];
        #pragma unroll
        for (int nt = 0; nt < 4; ++nt)
            #pragma unroll
            for (int i = 0; i < 4; ++i) { s0[nt][i] = 0.f; s1[nt][i] = 0.f; }

        #pragma unroll
        for (int ks = 0; ks < 8; ++ks) {
            const int col = ks * 8 + c4;
            #pragma unroll
            for (int nt = 0; nt < 4; ++nt) {
                unsigned bf[2];
                bf[0] = Ks[cur][nt * 8 + g][col];
                bf[1] = Ks[cur][nt * 8 + g][col + 4];
                mma_tf32(s0[nt], qf0[ks], bf, s0[nt]);
                mma_tf32(s1[nt], qf1[ks], bf, s1[nt]);
            }
        }

        // ---- interleaved fixed-base softmax + PV, per column group ----
        #pragma unroll
        for (int grp = 0; grp < 4; ++grp) {
            const int col = grp * 8 + c4;

            // V fragments: independent of softmax; load during the ex2 chain
            unsigned vf[8][2];
            #pragma unroll
            for (int nt2 = 0; nt2 < 8; ++nt2) {
                vf[nt2][0] = Vs[cur][col][g + 8 * nt2];
                vf[nt2][1] = Vs[cur][col + 4][g + 8 * nt2];
            }

            // fixed-base softmax for group grp (q pre-scaled: p = 2^s)
            {
                float p0 = ex2(s0[grp][0]);
                float p1 = ex2(s0[grp][1]);
                float p2 = ex2(s0[grp][2]);
                float p3 = ex2(s0[grp][3]);
                l00 += p0 + p1; l01 += p2 + p3;
                *(uint2*)&Ps[rb + g][grp * 8 + 2 * c4] =
                    make_uint2(__float_as_uint(p0), __float_as_uint(p1));
                *(uint2*)&Ps[rb + g + 8][grp * 8 + 2 * c4] =
                    make_uint2(__float_as_uint(p2), __float_as_uint(p3));

                p0 = ex2(s1[grp][0]);
                p1 = ex2(s1[grp][1]);
                p2 = ex2(s1[grp][2]);
                p3 = ex2(s1[grp][3]);
                l10 += p0 + p1; l11 += p2 + p3;
                *(uint2*)&Ps[rb + 16 + g][grp * 8 + 2 * c4] =
                    make_uint2(__float_as_uint(p0), __float_as_uint(p1));
                *(uint2*)&Ps[rb + 24 + g][grp * 8 + 2 * c4] =
                    make_uint2(__float_as_uint(p2), __float_as_uint(p3));
            }
            __syncwarp();   // group grp's Ps stores visible within warp

            // PV ks-step = grp
            {
                unsigned pf0[4], pf1[4];
                pf0[0] = Ps[rb + g][col];
                pf0[1] = Ps[rb + g + 8][col];
                pf0[2] = Ps[rb + g][col + 4];
                pf0[3] = Ps[rb + g + 8][col + 4];
                pf1[0] = Ps[rb + 16 + g][col];
                pf1[1] = Ps[rb + 24 + g][col];
                pf1[2] = Ps[rb + 16 + g][col + 4];
                pf1[3] = Ps[rb + 24 + g][col + 4];
                #pragma unroll
                for (int nt2 = 0; nt2 < 8; ++nt2) {
                    mma_tf32(o0[nt2], pf0, vf[nt2], o0[nt2]);
                    mma_tf32(o1[nt2], pf1, vf[nt2], o1[nt2]);
                }
            }
        }

        cur = (cur + 1 == 3) ? 0 : cur + 1;
        fil = (fil + 1 == 3) ? 0 : fil + 1;
    }

    // ---- final l reduction (once) ----
    #pragma unroll
    for (int d = 1; d <= 2; d <<= 1) {
        l00 += __shfl_xor_sync(0xffffffffu, l00, d);
        l01 += __shfl_xor_sync(0xffffffffu, l01, d);
        l10 += __shfl_xor_sync(0xffffffffu, l10, d);
        l11 += __shfl_xor_sync(0xffffffffu, l11, d);
    }

    // ---- finalize: divide by l, RNA-round to tf32 grid, write ctx ----
    const float i00 = 1.f / l00, i01 = 1.f / l01;
    const float i10 = 1.f / l10, i11 = 1.f / l11;
    const int r0 = q0 + rb + g;
    #pragma unroll
    for (int nt = 0; nt < 8; ++nt) {
        const int col = h * DK + nt * 8 + 2 * c4;
        float2 w;
        w.x = __uint_as_float(f2tf32(o0[nt][0] * i00));
        w.y = __uint_as_float(f2tf32(o0[nt][1] * i00));
        *(float2*)&Ctx[((size_t)b * SS + r0) * DD + col] = w;
        w.x = __uint_as_float(f2tf32(o0[nt][2] * i01));
        w.y = __uint_as_float(f2tf32(o0[nt][3] * i01));
        *(float2*)&Ctx[((size_t)b * SS + r0 + 8) * DD + col] = w;
        w.x = __uint_as_float(f2tf32(o1[nt][0] * i10));
        w.y = __uint_as_float(f2tf32(o1[nt][1] * i10));
        *(float2*)&Ctx[((size_t)b * SS + r0 + 16) * DD + col] = w;
        w.x = __uint_as_float(f2tf32(o1[nt][2] * i11));
        w.y = __uint_as_float(f2tf32(o1[nt][3] * i11));
        *(float2*)&Ctx[((size_t)b * SS + r0 + 24) * DD + col] = w;
    }
}

// ---------------------------------------------------------------------------
// Launch
// ---------------------------------------------------------------------------
extern "C" void kernel_launch(void* const* d_in, const int* in_sizes, int n_in,
                              void* d_out, int out_size)
{
    const float* query = (const float*)d_in[0];
    const float* key   = (const float*)d_in[1];
    const float* value = (const float*)d_in[2];
    const float* Wq    = (const float*)d_in[3];
    const float* Wk    = (const float*)d_in[4];
    const float* Wv    = (const float*)d_in[5];
    const float* Wo    = (const float*)d_in[6];

    float *gq, *gk, *gv, *gc, *gqa, *gka, *gva, *gwq, *gwk, *gwv, *gwo;
    cudaGetSymbolAddress((void**)&gq,  g_q);
    cudaGetSymbolAddress((void**)&gk,  g_k);
    cudaGetSymbolAddress((void**)&gv,  g_v);
    cudaGetSymbolAddress((void**)&gc,  g_ctx);
    cudaGetSymbolAddress((void**)&gqa, g_qa);
    cudaGetSymbolAddress((void**)&gka, g_ka);
    cudaGetSymbolAddress((void**)&gva, g_va);
    cudaGetSymbolAddress((void**)&gwq, g_wq);
    cudaGetSymbolAddress((void**)&gwk, g_wk);
    cudaGetSymbolAddress((void**)&gwv, g_wv);
    cudaGetSymbolAddress((void**)&gwo, g_wo);

    // ---- pre-round all GEMM operands onto the tf32 grid (RNA), fused ----
    const int act4 = MM * DD / 4;   // 2M float4
    const int w4   = DD * DD / 4;   // 256K float4
    {
        dim3 grid_a((act4 + 255) / 256, 1, 3);
        round_tf32_x3<<<grid_a, 256>>>(
            (const float4*)query, (const float4*)key, (const float4*)value,
            (float4*)gqa, (float4*)gka, (float4*)gva, act4);
        dim3 grid_w((w4 + 255) / 256, 1, 4);
        round_tf32_x4<<<grid_w, 256>>>(
            (const float4*)Wq, (const float4*)Wk, (const float4*)Wv, (const float4*)Wo,
            (float4*)gwq, (float4*)gwk, (float4*)gwv, (float4*)gwo, w4);
    }

    cudaFuncSetAttribute(gemm_tf32_relu_v5,
                         cudaFuncAttributeMaxDynamicSharedMemorySize,
                         GEMM_SMEM_BYTES);

    // ---- fused QKV projections (q output carries QSCALE) ----
    {
        dim3 grid(DD / 128, MM / 128, 3);   // (8, 64, 3)
        gemm_tf32_relu_v5<<<grid, 128, GEMM_SMEM_BYTES>>>(
            gqa, gwq, gq,
            gka, gwk, gk,
            gva, gwv, gv,
            MM, DD, DD, QSCALE);
    }

    cudaFuncSetAttribute(attention_tc,
                         cudaFuncAttributeMaxDynamicSharedMemorySize,
                         ATT_SMEM_BYTES);
    attention_tc<<<dim3(SS / QTILE, BB * NHEAD), 128, ATT_SMEM_BYTES>>>(gq, gk, gv, gc);

    // ---- output projection (no epilogue scale) ----
    {
        dim3 grid(DD / 128, MM / 128, 1);
        gemm_tf32_relu_v5<<<grid, 128, GEMM_SMEM_BYTES>>>(
            gc, gwo, (float*)d_out,
            gc, gwo, (float*)d_out,
            gc, gwo, (float*)d_out,
            MM, DD, DD, 1.0f);
    }
}